// round 6
// baseline (speedup 1.0000x reference)
#include <cuda_runtime.h>
#include <cstdint>

#define N_MAX 8192
#define D_MAX 256
#define BM 128
#define BN 128
#define BK 64                      // int8 bytes of K per stage
#define NTHREADS 256
#define MARGIN 0.5f
#define QSCALE 16.0f
#define INV_QS2 (1.0f / (QSCALE * QSCALE))

__device__ char  g_xq[N_MAX * D_MAX];   // int8 quantized X
__device__ float g_sq[N_MAX];           // exact fp32 row norms
__device__ int   g_is64;

__device__ __forceinline__ uint32_t smem_u32(const void* p) {
    uint32_t a;
    asm("{ .reg .u64 t; cvta.to.shared.u64 t, %1; cvt.u32.u64 %0, t; }" : "=r"(a) : "l"(p));
    return a;
}

// ---------------------------------------------------------------------------
// fused prelim: block 0 warp 0 zeroes out + detects int64 targets (parallel);
// every warp computes one row: exact fp32 norm + int8 quantized copy.
// ---------------------------------------------------------------------------
__global__ void cvtsq_kernel(const float* __restrict__ x,
                             const unsigned int* __restrict__ t, int n,
                             float* __restrict__ out) {
    if (blockIdx.x == 0 && threadIdx.x < 32) {
        int lane = threadIdx.x;
        // check odd 32-bit words of the first 64 labels (2 per lane)
        unsigned bad = t[2 * lane + 1] | t[2 * (lane + 32) + 1];
        unsigned ball = __ballot_sync(0xffffffffu, bad != 0u);
        if (lane == 0) { g_is64 = (ball == 0u); out[0] = 0.0f; }
    }

    int row  = blockIdx.x * (blockDim.x >> 5) + (threadIdx.x >> 5);
    int lane = threadIdx.x & 31;
    if (row >= n) return;
    const float* p = x + (size_t)row * D_MAX;

    float4 v0 = *(const float4*)(p + lane * 4);
    float4 v1 = *(const float4*)(p + 128 + lane * 4);

    float s = v0.x * v0.x + v0.y * v0.y + v0.z * v0.z + v0.w * v0.w
            + v1.x * v1.x + v1.y * v1.y + v1.z * v1.z + v1.w * v1.w;
    #pragma unroll
    for (int o = 16; o > 0; o >>= 1) s += __shfl_xor_sync(0xffffffffu, s, o);
    if (lane == 0) g_sq[row] = s;

    auto q8 = [](float f) -> int {
        float q = fminf(fmaxf(rintf(f * QSCALE), -127.0f), 127.0f);
        return (int)q;
    };
    uint32_t w0 = (uint32_t)(q8(v0.x) & 255) | ((uint32_t)(q8(v0.y) & 255) << 8)
                | ((uint32_t)(q8(v0.z) & 255) << 16) | ((uint32_t)(q8(v0.w) & 255) << 24);
    uint32_t w1 = (uint32_t)(q8(v1.x) & 255) | ((uint32_t)(q8(v1.y) & 255) << 8)
                | ((uint32_t)(q8(v1.z) & 255) << 16) | ((uint32_t)(q8(v1.w) & 255) << 24);
    uint32_t* dst = (uint32_t*)(g_xq + (size_t)row * D_MAX);
    dst[lane] = w0;
    dst[32 + lane] = w1;
}

// ---------------------------------------------------------------------------
// int8 IMMA fused gram + loss, double-buffered cp.async pipeline (R3 structure).
// Stage = BK=64 K-bytes of both tiles (16 KB). smem row stride 64B, 4 chunks of
// 16B; chunk c of row r at r*64 + ((c ^ (r&3))<<4)  -> conflict-free.
// ---------------------------------------------------------------------------
__global__ __launch_bounds__(NTHREADS, 2)
void loss_kernel(const void* __restrict__ tgt_raw, float* __restrict__ out,
                 int nt, float scale) {
    // exact triangular decode t -> (bi, bj), bj >= bi
    const int t = blockIdx.x;
    int b = (int)((2.0f * nt + 1.0f -
                   sqrtf((2.0f * nt + 1.0f) * (2.0f * nt + 1.0f) - 8.0f * t)) * 0.5f);
    if (b < 0) b = 0;
    if (b > nt - 1) b = nt - 1;
    while (b + 1 <= nt - 1 && (b + 1) * nt - ((b + 1) * b) / 2 <= t) b++;
    while (b * nt - (b * (b - 1)) / 2 > t) b--;
    const int bi = b;
    const int bj = bi + (t - (bi * nt - (bi * (bi - 1)) / 2));

    __shared__ char  s_tiles[2 * 2 * BM * BK];      // [stage][A|B] = 32 KB
    __shared__ float s_sqi[BM], s_sqj[BN];
    __shared__ int   s_ti[BM], s_tj[BN];
    __shared__ float s_red[NTHREADS];

    const int tid  = threadIdx.x;
    const int wid  = tid >> 5;
    const int lane = tid & 31;
    const long iBase = (long)bi * BM;
    const long jBase = (long)bj * BN;

    {
        const long long* t64p = (const long long*)tgt_raw;
        const int*       t32p = (const int*)tgt_raw;
        const bool is64 = (g_is64 != 0);
        if (tid < BM) {
            s_sqi[tid] = g_sq[iBase + tid];
            s_ti[tid]  = is64 ? (int)t64p[iBase + tid] : t32p[iBase + tid];
        } else {
            int tt = tid - BM;
            s_sqj[tt] = g_sq[jBase + tt];
            s_tj[tt]  = is64 ? (int)t64p[jBase + tt] : t32p[jBase + tt];
        }
    }

    const uint32_t smem_tiles = smem_u32(s_tiles);
    const uint32_t stage_bytes = 2 * BM * BK;       // 16 KB
    const char* xa = g_xq + iBase * D_MAX;
    const char* xb = g_xq + jBase * D_MAX;

    // 2 chunks of A + 2 of B per thread per stage (idx = tid*2+t, 0..511)
    auto load_stage = [&](int kb, int stage) {
        const int k0 = kb * BK;
        const uint32_t sA = smem_tiles + stage * stage_bytes;
        const uint32_t sB = sA + BM * BK;
        #pragma unroll
        for (int u = 0; u < 2; u++) {
            int idx = tid * 2 + u;
            int row = idx >> 2;
            int c   = idx & 3;
            uint32_t sw = row * 64 + (((c ^ (row & 3)) & 3) << 4);
            asm volatile("cp.async.cg.shared.global [%0], [%1], 16;"
                         :: "r"(sA + sw), "l"((const void*)(xa + row * D_MAX + k0 + c * 16)) : "memory");
            asm volatile("cp.async.cg.shared.global [%0], [%1], 16;"
                         :: "r"(sB + sw), "l"((const void*)(xb + row * D_MAX + k0 + c * 16)) : "memory");
        }
        asm volatile("cp.async.commit_group;" ::: "memory");
    };

    // warp layout: 4 (m) x 2 (n); warp tile 32 x 64
    const int mbase = (wid >> 1) * 32;
    const int nbase = (wid & 1) * 64;

    int acc[2][8][4];
    #pragma unroll
    for (int mt = 0; mt < 2; mt++)
        #pragma unroll
        for (int ntl = 0; ntl < 8; ntl++)
            #pragma unroll
            for (int r = 0; r < 4; r++) acc[mt][ntl][r] = 0;

    // ldmatrix lane -> (row, 16B-chunk) components (validated in R3/R4)
    const int a_roff = ((lane >> 3) & 1) * 8 + (lane & 7);
    const int a_coff = (lane >> 4);
    const int b_roff = ((lane >> 4) & 1) * 8 + (lane & 7);
    const int b_coff = ((lane >> 3) & 1);

    load_stage(0, 0);

    const int NKB = D_MAX / BK;   // 4 stages
    for (int kb = 0; kb < NKB; kb++) {
        if (kb + 1 < NKB) {
            load_stage(kb + 1, (kb + 1) & 1);
            asm volatile("cp.async.wait_group 1;" ::: "memory");
        } else {
            asm volatile("cp.async.wait_group 0;" ::: "memory");
        }
        __syncthreads();

        const uint32_t sA = smem_tiles + (kb & 1) * stage_bytes;
        const uint32_t sB = sA + BM * BK;

        #pragma unroll
        for (int ks = 0; ks < 2; ks++) {           // two k32 steps per stage
            uint32_t a[2][4];
            #pragma unroll
            for (int mt = 0; mt < 2; mt++) {
                int r  = mbase + mt * 16 + a_roff;
                int ch = a_coff + 2 * ks;
                uint32_t addr = sA + r * 64 + (((ch ^ (r & 3)) & 3) << 4);
                asm volatile("ldmatrix.sync.aligned.m8n8.x4.shared.b16 {%0,%1,%2,%3}, [%4];"
                             : "=r"(a[mt][0]), "=r"(a[mt][1]), "=r"(a[mt][2]), "=r"(a[mt][3])
                             : "r"(addr));
            }
            uint32_t bfr[8][2];
            #pragma unroll
            for (int p = 0; p < 4; p++) {
                int r  = nbase + p * 16 + b_roff;
                int ch = b_coff + 2 * ks;
                uint32_t addr = sB + r * 64 + (((ch ^ (r & 3)) & 3) << 4);
                asm volatile("ldmatrix.sync.aligned.m8n8.x4.shared.b16 {%0,%1,%2,%3}, [%4];"
                             : "=r"(bfr[2 * p][0]), "=r"(bfr[2 * p][1]),
                               "=r"(bfr[2 * p + 1][0]), "=r"(bfr[2 * p + 1][1])
                             : "r"(addr));
            }
            #pragma unroll
            for (int mt = 0; mt < 2; mt++)
                #pragma unroll
                for (int ntl = 0; ntl < 8; ntl++)
                    asm volatile(
                        "mma.sync.aligned.m16n8k32.row.col.s32.s8.s8.s32 "
                        "{%0,%1,%2,%3}, {%4,%5,%6,%7}, {%8,%9}, {%0,%1,%2,%3};"
                        : "+r"(acc[mt][ntl][0]), "+r"(acc[mt][ntl][1]),
                          "+r"(acc[mt][ntl][2]), "+r"(acc[mt][ntl][3])
                        : "r"(a[mt][0]), "r"(a[mt][1]), "r"(a[mt][2]), "r"(a[mt][3]),
                          "r"(bfr[ntl][0]), "r"(bfr[ntl][1]));
        }
        __syncthreads();
    }

    // epilogue: dist = sqi + sqj - 2*acc/QSCALE^2; hinge; strict-upper sum
    const int gid = lane >> 2;
    const int tig = lane & 3;
    const bool diag = (bi == bj);
    const float k2 = -2.0f * INV_QS2;
    float lsum = 0.0f;
    #pragma unroll
    for (int mt = 0; mt < 2; mt++) {
        #pragma unroll
        for (int ntl = 0; ntl < 8; ntl++) {
            #pragma unroll
            for (int r = 0; r < 4; r++) {
                int m  = mbase + mt * 16 + gid + ((r >> 1) << 3);
                int nn = nbase + ntl * 8 + 2 * tig + (r & 1);
                float g    = (float)acc[mt][ntl][r];
                float dist = fmaf(k2, g, s_sqi[m] + s_sqj[nn]);
                float val  = (s_ti[m] == s_tj[nn]) ? dist : fmaxf(MARGIN - dist, 0.0f);
                if (!diag || (m < nn)) lsum += val;
            }
        }
    }

    // block reduce + one atomic
    s_red[tid] = lsum;
    __syncthreads();
    #pragma unroll
    for (int s = NTHREADS / 2; s > 32; s >>= 1) {
        if (tid < s) s_red[tid] += s_red[tid + s];
        __syncthreads();
    }
    if (tid < 32) {
        float v = s_red[tid] + s_red[tid + 32];
        #pragma unroll
        for (int o = 16; o > 0; o >>= 1) v += __shfl_xor_sync(0xffffffffu, v, o);
        if (tid == 0) atomicAdd(out, v * scale);
    }
}

extern "C" void kernel_launch(void* const* d_in, const int* in_sizes, int n_in,
                              void* d_out, int out_size) {
    const float* x   = (const float*)d_in[0];
    const void*  tgt = d_in[1];
    float*       out = (float*)d_out;

    int n = in_sizes[1];          // 8192
    int nt = n / BM;              // 64
    int ntri = nt * (nt + 1) / 2; // 2080

    cvtsq_kernel<<<(n + 7) / 8, 256>>>(x, (const unsigned int*)tgt, n, out);

    float scale = (float)(1.0 / ((double)n * ((double)n - 1.0)));
    loss_kernel<<<ntri, NTHREADS>>>(tgt, out, nt, scale);
}

// round 7
// speedup vs baseline: 1.4688x; 1.4688x over previous
#include <cuda_runtime.h>
#include <cuda_bf16.h>
#include <cstdint>

#define N_MAX 8192
#define D_MAX 256
#define BM 128
#define BN 128
#define BK 32                     // bf16 elements of K per stage
#define KSTAGES 2
#define NTHREADS 256
#define MARGIN 0.5f

__device__ __nv_bfloat16 g_xbf[N_MAX * D_MAX];
__device__ float g_sq[N_MAX];
__device__ int   g_is64;

__device__ __forceinline__ uint32_t smem_u32(const void* p) {
    uint32_t a;
    asm("{ .reg .u64 t; cvta.to.shared.u64 t, %1; cvt.u32.u64 %0, t; }" : "=r"(a) : "l"(p));
    return a;
}

// ---------------------------------------------------------------------------
// fused prelim: block 0 warp 0 zeroes out + detects int64 targets; every warp
// handles one row: exact fp32 norm + bf16 converted copy. One launch total.
// ---------------------------------------------------------------------------
__global__ void cvtsq_kernel(const float* __restrict__ x,
                             const unsigned int* __restrict__ t, int n,
                             float* __restrict__ out) {
    if (blockIdx.x == 0 && threadIdx.x < 32) {
        int lane = threadIdx.x;
        unsigned bad = t[2 * lane + 1] | t[2 * (lane + 32) + 1];
        unsigned ball = __ballot_sync(0xffffffffu, bad != 0u);
        if (lane == 0) { g_is64 = (ball == 0u); out[0] = 0.0f; }
    }

    int row  = blockIdx.x * (blockDim.x >> 5) + (threadIdx.x >> 5);
    int lane = threadIdx.x & 31;
    if (row >= n) return;
    const float* p = x + (size_t)row * D_MAX;

    float4 v0 = *(const float4*)(p + lane * 4);
    float4 v1 = *(const float4*)(p + 128 + lane * 4);

    float s = v0.x * v0.x + v0.y * v0.y + v0.z * v0.z + v0.w * v0.w
            + v1.x * v1.x + v1.y * v1.y + v1.z * v1.z + v1.w * v1.w;
    #pragma unroll
    for (int o = 16; o > 0; o >>= 1) s += __shfl_xor_sync(0xffffffffu, s, o);
    if (lane == 0) g_sq[row] = s;

    __nv_bfloat16* dst = g_xbf + (size_t)row * D_MAX;
    *(__nv_bfloat162*)(dst + lane * 4)       = __floats2bfloat162_rn(v0.x, v0.y);
    *(__nv_bfloat162*)(dst + lane * 4 + 2)   = __floats2bfloat162_rn(v0.z, v0.w);
    *(__nv_bfloat162*)(dst + 128 + lane * 4)     = __floats2bfloat162_rn(v1.x, v1.y);
    *(__nv_bfloat162*)(dst + 128 + lane * 4 + 2) = __floats2bfloat162_rn(v1.z, v1.w);
}

// ---------------------------------------------------------------------------
// bf16 mma.sync fused gram + contrastive loss (R3 structure, proven 92us).
// One CTA per 128x128 upper-triangular tile, exact triangular grid.
// smem tile rows: 64B stride, 16B chunk c of row r at r*64 + ((c^(r&3))<<4).
// ---------------------------------------------------------------------------
__global__ __launch_bounds__(NTHREADS, 2)
void loss_kernel(const void* __restrict__ tgt_raw, float* __restrict__ out,
                 int nt, float scale) {
    // triangular decode t -> (bi, bj), bj >= bi   (validated R5/R6)
    const int t = blockIdx.x;
    int b = (int)((2.0f * nt + 1.0f -
                   sqrtf((2.0f * nt + 1.0f) * (2.0f * nt + 1.0f) - 8.0f * t)) * 0.5f);
    if (b < 0) b = 0;
    if (b > nt - 1) b = nt - 1;
    while (b + 1 <= nt - 1 && (b + 1) * nt - ((b + 1) * b) / 2 <= t) b++;
    while (b * nt - (b * (b - 1)) / 2 > t) b--;
    const int bi = b;
    const int bj = bi + (t - (bi * nt - (bi * (bi - 1)) / 2));

    __shared__ char  s_tiles[KSTAGES * 2 * BM * BK * 2];  // A then B per stage
    __shared__ float s_sqi[BM], s_sqj[BN];
    __shared__ int   s_ti[BM], s_tj[BN];
    __shared__ float s_red[NTHREADS];

    const int tid  = threadIdx.x;
    const int wid  = tid >> 5;
    const int lane = tid & 31;
    const long iBase = (long)bi * BM;
    const long jBase = (long)bj * BN;

    {
        const long long* t64p = (const long long*)tgt_raw;
        const int*       t32p = (const int*)tgt_raw;
        const bool is64 = (g_is64 != 0);
        if (tid < BM) {
            s_sqi[tid] = g_sq[iBase + tid];
            s_ti[tid]  = is64 ? (int)t64p[iBase + tid] : t32p[iBase + tid];
        } else {
            int tt = tid - BM;
            s_sqj[tt] = g_sq[jBase + tt];
            s_tj[tt]  = is64 ? (int)t64p[jBase + tt] : t32p[jBase + tt];
        }
    }

    const uint32_t smem_tiles = smem_u32(s_tiles);
    const uint32_t stage_bytes = 2 * BM * BK * 2;          // 16 KB
    const __nv_bfloat16* xa = g_xbf + iBase * D_MAX;
    const __nv_bfloat16* xb = g_xbf + jBase * D_MAX;

    auto load_stage = [&](int kb, int stage) {
        const int k0 = kb * BK;
        const uint32_t sA = smem_tiles + stage * stage_bytes;
        const uint32_t sB = sA + BM * BK * 2;
        #pragma unroll
        for (int u = 0; u < 2; u++) {
            int idx = tid * 2 + u;
            int row = idx >> 2;
            int c   = idx & 3;
            uint32_t sw = row * 64 + (((c ^ (row & 3)) & 3) << 4);
            asm volatile("cp.async.cg.shared.global [%0], [%1], 16;"
                         :: "r"(sA + sw), "l"((const void*)(xa + row * D_MAX + k0 + c * 8)) : "memory");
            asm volatile("cp.async.cg.shared.global [%0], [%1], 16;"
                         :: "r"(sB + sw), "l"((const void*)(xb + row * D_MAX + k0 + c * 8)) : "memory");
        }
        asm volatile("cp.async.commit_group;" ::: "memory");
    };

    // warp layout: 4 (m) x 2 (n); warp tile 32 x 64
    const int mbase = (wid >> 1) * 32;
    const int nbase = (wid & 1) * 64;

    float acc[2][8][4];
    #pragma unroll
    for (int mt = 0; mt < 2; mt++)
        #pragma unroll
        for (int ntl = 0; ntl < 8; ntl++)
            #pragma unroll
            for (int r = 0; r < 4; r++) acc[mt][ntl][r] = 0.0f;

    const int a_roff = ((lane >> 3) & 1) * 8 + (lane & 7);
    const int a_coff = (lane >> 4);
    const int b_roff = ((lane >> 4) & 1) * 8 + (lane & 7);
    const int b_coff = ((lane >> 3) & 1);

    load_stage(0, 0);

    const int NKB = D_MAX / BK;   // 8
    for (int kb = 0; kb < NKB; kb++) {
        if (kb + 1 < NKB) {
            load_stage(kb + 1, (kb + 1) & 1);
            asm volatile("cp.async.wait_group 1;" ::: "memory");
        } else {
            asm volatile("cp.async.wait_group 0;" ::: "memory");
        }
        __syncthreads();

        const uint32_t sA = smem_tiles + (kb & 1) * stage_bytes;
        const uint32_t sB = sA + BM * BK * 2;

        #pragma unroll
        for (int ks = 0; ks < 2; ks++) {
            uint32_t a[2][4];
            #pragma unroll
            for (int mt = 0; mt < 2; mt++) {
                int r = mbase + mt * 16 + a_roff;
                int c = a_coff + 2 * ks;
                uint32_t addr = sA + r * 64 + (((c ^ (r & 3)) & 3) << 4);
                asm volatile("ldmatrix.sync.aligned.m8n8.x4.shared.b16 {%0,%1,%2,%3}, [%4];"
                             : "=r"(a[mt][0]), "=r"(a[mt][1]), "=r"(a[mt][2]), "=r"(a[mt][3])
                             : "r"(addr));
            }
            uint32_t bfr[8][2];
            #pragma unroll
            for (int p = 0; p < 4; p++) {
                int r = nbase + p * 16 + b_roff;
                int c = b_coff + 2 * ks;
                uint32_t addr = sB + r * 64 + (((c ^ (r & 3)) & 3) << 4);
                asm volatile("ldmatrix.sync.aligned.m8n8.x4.shared.b16 {%0,%1,%2,%3}, [%4];"
                             : "=r"(bfr[2 * p][0]), "=r"(bfr[2 * p][1]),
                               "=r"(bfr[2 * p + 1][0]), "=r"(bfr[2 * p + 1][1])
                             : "r"(addr));
            }
            #pragma unroll
            for (int mt = 0; mt < 2; mt++)
                #pragma unroll
                for (int ntl = 0; ntl < 8; ntl++)
                    asm volatile(
                        "mma.sync.aligned.m16n8k16.row.col.f32.bf16.bf16.f32 "
                        "{%0,%1,%2,%3}, {%4,%5,%6,%7}, {%8,%9}, {%0,%1,%2,%3};"
                        : "+f"(acc[mt][ntl][0]), "+f"(acc[mt][ntl][1]),
                          "+f"(acc[mt][ntl][2]), "+f"(acc[mt][ntl][3])
                        : "r"(a[mt][0]), "r"(a[mt][1]), "r"(a[mt][2]), "r"(a[mt][3]),
                          "r"(bfr[ntl][0]), "r"(bfr[ntl][1]));
        }
        __syncthreads();
    }

    // epilogue: dist -> hinge/mask -> strict-upper sum
    const int gid = lane >> 2;
    const int tig = lane & 3;
    const bool diag = (bi == bj);
    float lsum = 0.0f;
    #pragma unroll
    for (int mt = 0; mt < 2; mt++) {
        #pragma unroll
        for (int ntl = 0; ntl < 8; ntl++) {
            #pragma unroll
            for (int r = 0; r < 4; r++) {
                int m  = mbase + mt * 16 + gid + ((r >> 1) << 3);
                int nn = nbase + ntl * 8 + 2 * tig + (r & 1);
                float g    = acc[mt][ntl][r];
                float dist = fmaf(-2.0f, g, s_sqi[m] + s_sqj[nn]);
                float val  = (s_ti[m] == s_tj[nn]) ? dist : fmaxf(MARGIN - dist, 0.0f);
                if (!diag || (m < nn)) lsum += val;
            }
        }
    }

    s_red[tid] = lsum;
    __syncthreads();
    #pragma unroll
    for (int s = NTHREADS / 2; s > 32; s >>= 1) {
        if (tid < s) s_red[tid] += s_red[tid + s];
        __syncthreads();
    }
    if (tid < 32) {
        float v = s_red[tid] + s_red[tid + 32];
        #pragma unroll
        for (int o = 16; o > 0; o >>= 1) v += __shfl_xor_sync(0xffffffffu, v, o);
        if (tid == 0) atomicAdd(out, v * scale);
    }
}

extern "C" void kernel_launch(void* const* d_in, const int* in_sizes, int n_in,
                              void* d_out, int out_size) {
    const float* x   = (const float*)d_in[0];
    const void*  tgt = d_in[1];
    float*       out = (float*)d_out;

    int n = in_sizes[1];          // 8192
    int nt = n / BM;              // 64
    int ntri = nt * (nt + 1) / 2; // 2080

    cvtsq_kernel<<<(n + 7) / 8, 256>>>(x, (const unsigned int*)tgt, n, out);

    float scale = (float)(1.0 / ((double)n * ((double)n - 1.0)));
    loss_kernel<<<ntri, NTHREADS>>>(tgt, out, nt, scale);
}